// round 4
// baseline (speedup 1.0000x reference)
#include <cuda_runtime.h>
#include <cuda_bf16.h>

#define N_NODES 100000
#define N_EDGES 3200000
#define E_TOT   (N_EDGES + N_NODES)
#define NEG_SLOPE 0.2f

// ---------------- device scratch (allocation-free contract) ----------------
__device__ int g_cnt[N_NODES];
__device__ int g_off[N_NODES + 1];
__device__ int g_cursor[N_NODES];
__device__ int g_csr_src[E_TOT];

__device__ float g_h1[N_NODES * 64];                 // layer-1 node features
__device__ __align__(16) float g_al1[N_NODES * 4];   // [als0, als1, ald0, ald1]
__device__ float g_hin2[N_NODES * 64];               // relu(layer-1 out) = layer-2 input
__device__ float g_h2[N_NODES * 64];                 // layer-2 node features
__device__ __align__(8) float g_al2[N_NODES * 2];    // [als, ald]

// ---------------- CSR build ----------------
__global__ void k_init() {
    int i = blockIdx.x * blockDim.x + threadIdx.x;
    if (i < N_NODES) g_cnt[i] = 1;   // self-loop pre-counted
}

__global__ void k_hist(const int* __restrict__ ei) {
    int e = blockIdx.x * blockDim.x + threadIdx.x;
    if (e < N_EDGES) atomicAdd(&g_cnt[ei[N_EDGES + e]], 1);   // dst row
}

// single-block sequential-tile exclusive scan over g_cnt -> g_off, g_cursor
__global__ void k_scan() {
    __shared__ int warp_sums[32];
    __shared__ int s_carry;
    int tid = threadIdx.x, lane = tid & 31, wid = tid >> 5;
    if (tid == 0) s_carry = 0;
    __syncthreads();
    for (int base = 0; base < N_NODES; base += 1024) {
        int i = base + tid;
        int v = (i < N_NODES) ? g_cnt[i] : 0;
        int x = v;
        #pragma unroll
        for (int d = 1; d < 32; d <<= 1) {
            int y = __shfl_up_sync(0xFFFFFFFFu, x, d);
            if (lane >= d) x += y;
        }
        if (lane == 31) warp_sums[wid] = x;
        __syncthreads();
        if (wid == 0) {
            int y = warp_sums[lane];
            #pragma unroll
            for (int d = 1; d < 32; d <<= 1) {
                int z = __shfl_up_sync(0xFFFFFFFFu, y, d);
                if (lane >= d) y += z;
            }
            warp_sums[lane] = y;
        }
        __syncthreads();
        int incl = x + (wid > 0 ? warp_sums[wid - 1] : 0);
        int excl = incl - v;
        int carry = s_carry;
        if (i < N_NODES) { g_off[i] = carry + excl; g_cursor[i] = carry + excl; }
        __syncthreads();
        if (tid == 1023) s_carry = carry + warp_sums[31];
        __syncthreads();
    }
    if (tid == 0) g_off[N_NODES] = E_TOT;
}

__global__ void k_scatter(const int* __restrict__ ei) {
    int e = blockIdx.x * blockDim.x + threadIdx.x;
    if (e >= E_TOT) return;
    int src, dst;
    if (e < N_EDGES) { src = ei[e]; dst = ei[N_EDGES + e]; }
    else             { src = dst = e - N_EDGES; }   // self loop
    int pos = atomicAdd(&g_cursor[dst], 1);
    g_csr_src[pos] = src;
}

// ---------------- layer 1: node transform (xin @ W1, attention scalars) ----
__global__ void k_node1(const float* __restrict__ x, const int* __restrict__ tids,
                        const float* __restrict__ temb, const float* __restrict__ W1,
                        const float* __restrict__ as1, const float* __restrict__ ad1) {
    __shared__ float sW[21 * 64];
    __shared__ float sxin[4][21];
    int t = threadIdx.x;
    for (int i = t; i < 21 * 64; i += 256) sW[i] = W1[i];
    int nl = t >> 6, c = t & 63;
    int node = blockIdx.x * 4 + nl;
    if (node < N_NODES && c < 21)
        sxin[nl][c] = (c < 5) ? x[node * 5 + c] : temb[tids[node] * 16 + (c - 5)];
    __syncthreads();
    if (node >= N_NODES) return;
    float h = 0.f;
    #pragma unroll
    for (int k = 0; k < 21; k++) h += sxin[nl][k] * sW[k * 64 + c];
    g_h1[node * 64 + c] = h;
    int head = c >> 5;
    float ps = h * as1[c], pd = h * ad1[c];
    #pragma unroll
    for (int d = 16; d; d >>= 1) {
        ps += __shfl_xor_sync(0xFFFFFFFFu, ps, d);
        pd += __shfl_xor_sync(0xFFFFFFFFu, pd, d);
    }
    if ((c & 31) == 0) {
        g_al1[node * 4 + head]     = ps;   // a_src contribution
        g_al1[node * 4 + 2 + head] = pd;   // a_dst contribution
    }
}

// ---------------- layer 1: aggregation (warp per dst, fused softmax) -------
// 4-wide batched loads: raise MLP so the L2-latency chain overlaps.
__global__ void k_agg1(const float* __restrict__ b1) {
    int w = (blockIdx.x * blockDim.x + threadIdx.x) >> 5;
    int lane = threadIdx.x & 31;
    if (w >= N_NODES) return;
    int dst = w;
    float ald0 = g_al1[dst * 4 + 2], ald1 = g_al1[dst * 4 + 3];
    int beg = g_off[dst], end = g_off[dst + 1];
    float acc0 = 0.f, acc1 = 0.f, s0 = 0.f, s1 = 0.f;
    int p = beg;
    for (; p + 4 <= end; p += 4) {
        int i0 = __ldg(&g_csr_src[p]);
        int i1 = __ldg(&g_csr_src[p + 1]);
        int i2 = __ldg(&g_csr_src[p + 2]);
        int i3 = __ldg(&g_csr_src[p + 3]);
        float4 a0 = *reinterpret_cast<const float4*>(&g_al1[i0 * 4]);
        float4 a1 = *reinterpret_cast<const float4*>(&g_al1[i1 * 4]);
        float4 a2 = *reinterpret_cast<const float4*>(&g_al1[i2 * 4]);
        float4 a3 = *reinterpret_cast<const float4*>(&g_al1[i3 * 4]);
        float f00 = __ldg(&g_h1[i0 * 64 + lane]);
        float f01 = __ldg(&g_h1[i0 * 64 + 32 + lane]);
        float f10 = __ldg(&g_h1[i1 * 64 + lane]);
        float f11 = __ldg(&g_h1[i1 * 64 + 32 + lane]);
        float f20 = __ldg(&g_h1[i2 * 64 + lane]);
        float f21 = __ldg(&g_h1[i2 * 64 + 32 + lane]);
        float f30 = __ldg(&g_h1[i3 * 64 + lane]);
        float f31 = __ldg(&g_h1[i3 * 64 + 32 + lane]);
        float e;
        e = a0.x + ald0; e = (e > 0.f) ? e : NEG_SLOPE * e; float w00 = __expf(e);
        e = a0.y + ald1; e = (e > 0.f) ? e : NEG_SLOPE * e; float w01 = __expf(e);
        e = a1.x + ald0; e = (e > 0.f) ? e : NEG_SLOPE * e; float w10 = __expf(e);
        e = a1.y + ald1; e = (e > 0.f) ? e : NEG_SLOPE * e; float w11 = __expf(e);
        e = a2.x + ald0; e = (e > 0.f) ? e : NEG_SLOPE * e; float w20 = __expf(e);
        e = a2.y + ald1; e = (e > 0.f) ? e : NEG_SLOPE * e; float w21 = __expf(e);
        e = a3.x + ald0; e = (e > 0.f) ? e : NEG_SLOPE * e; float w30 = __expf(e);
        e = a3.y + ald1; e = (e > 0.f) ? e : NEG_SLOPE * e; float w31 = __expf(e);
        s0 += w00 + w10 + w20 + w30;
        s1 += w01 + w11 + w21 + w31;
        acc0 += w00 * f00 + w10 * f10 + w20 * f20 + w30 * f30;
        acc1 += w01 * f01 + w11 * f11 + w21 * f21 + w31 * f31;
    }
    for (; p < end; ++p) {
        int src = __ldg(&g_csr_src[p]);
        float4 a = *reinterpret_cast<const float4*>(&g_al1[src * 4]);
        float e0 = a.x + ald0; e0 = (e0 > 0.f) ? e0 : NEG_SLOPE * e0;
        float e1 = a.y + ald1; e1 = (e1 > 0.f) ? e1 : NEG_SLOPE * e1;
        float w0 = __expf(e0), w1 = __expf(e1);
        s0 += w0; s1 += w1;
        acc0 += w0 * __ldg(&g_h1[src * 64 + lane]);
        acc1 += w1 * __ldg(&g_h1[src * 64 + 32 + lane]);
    }
    float r0 = acc0 / (s0 + 1e-16f) + b1[lane];
    float r1 = acc1 / (s1 + 1e-16f) + b1[32 + lane];
    g_hin2[dst * 64 + lane]      = fmaxf(r0, 0.f);
    g_hin2[dst * 64 + 32 + lane] = fmaxf(r1, 0.f);
}

// ---------------- layer 2: node transform (hin2 @ W2, attention scalars) ---
__global__ void k_node2(const float* __restrict__ W2,
                        const float* __restrict__ as2, const float* __restrict__ ad2) {
    __shared__ float sW[64 * 64];
    __shared__ float shin[4][64];
    __shared__ float s_part[4][2][2];
    int t = threadIdx.x;
    for (int i = t; i < 64 * 64; i += 256) sW[i] = W2[i];
    int nl = t >> 6, c = t & 63;
    int node = blockIdx.x * 4 + nl;
    shin[nl][c] = g_hin2[node * 64 + c];
    __syncthreads();
    float h = 0.f;
    #pragma unroll
    for (int k = 0; k < 64; k++) h += shin[nl][k] * sW[k * 64 + c];
    g_h2[node * 64 + c] = h;
    float ps = h * as2[c], pd = h * ad2[c];
    #pragma unroll
    for (int d = 16; d; d >>= 1) {
        ps += __shfl_xor_sync(0xFFFFFFFFu, ps, d);
        pd += __shfl_xor_sync(0xFFFFFFFFu, pd, d);
    }
    if ((c & 31) == 0) { s_part[nl][c >> 5][0] = ps; s_part[nl][c >> 5][1] = pd; }
    __syncthreads();
    if (c == 0) {
        g_al2[node * 2 + 0] = s_part[nl][0][0] + s_part[nl][1][0];
        g_al2[node * 2 + 1] = s_part[nl][0][1] + s_part[nl][1][1];
    }
}

// ---------------- layer 2: aggregation + bias + LayerNorm -------------------
__global__ void k_agg2(const float* __restrict__ b2, const float* __restrict__ gamma,
                       const float* __restrict__ beta, float* __restrict__ out) {
    int w = (blockIdx.x * blockDim.x + threadIdx.x) >> 5;
    int lane = threadIdx.x & 31;
    if (w >= N_NODES) return;
    int dst = w;
    float ald = g_al2[dst * 2 + 1];
    int beg = g_off[dst], end = g_off[dst + 1];
    float acc0 = 0.f, acc1 = 0.f, s = 0.f;
    int p = beg;
    for (; p + 4 <= end; p += 4) {
        int i0 = __ldg(&g_csr_src[p]);
        int i1 = __ldg(&g_csr_src[p + 1]);
        int i2 = __ldg(&g_csr_src[p + 2]);
        int i3 = __ldg(&g_csr_src[p + 3]);
        float a0 = g_al2[i0 * 2];
        float a1 = g_al2[i1 * 2];
        float a2 = g_al2[i2 * 2];
        float a3 = g_al2[i3 * 2];
        float f00 = __ldg(&g_h2[i0 * 64 + lane]);
        float f01 = __ldg(&g_h2[i0 * 64 + 32 + lane]);
        float f10 = __ldg(&g_h2[i1 * 64 + lane]);
        float f11 = __ldg(&g_h2[i1 * 64 + 32 + lane]);
        float f20 = __ldg(&g_h2[i2 * 64 + lane]);
        float f21 = __ldg(&g_h2[i2 * 64 + 32 + lane]);
        float f30 = __ldg(&g_h2[i3 * 64 + lane]);
        float f31 = __ldg(&g_h2[i3 * 64 + 32 + lane]);
        float e;
        e = a0 + ald; e = (e > 0.f) ? e : NEG_SLOPE * e; float w0 = __expf(e);
        e = a1 + ald; e = (e > 0.f) ? e : NEG_SLOPE * e; float w1 = __expf(e);
        e = a2 + ald; e = (e > 0.f) ? e : NEG_SLOPE * e; float w2 = __expf(e);
        e = a3 + ald; e = (e > 0.f) ? e : NEG_SLOPE * e; float w3 = __expf(e);
        s += w0 + w1 + w2 + w3;
        acc0 += w0 * f00 + w1 * f10 + w2 * f20 + w3 * f30;
        acc1 += w0 * f01 + w1 * f11 + w2 * f21 + w3 * f31;
    }
    for (; p < end; ++p) {
        int src = __ldg(&g_csr_src[p]);
        float a = g_al2[src * 2];
        float e = a + ald; e = (e > 0.f) ? e : NEG_SLOPE * e;
        float wt = __expf(e);
        s += wt;
        acc0 += wt * __ldg(&g_h2[src * 64 + lane]);
        acc1 += wt * __ldg(&g_h2[src * 64 + 32 + lane]);
    }
    float inv = 1.f / (s + 1e-16f);
    float r0 = acc0 * inv + b2[lane];
    float r1 = acc1 * inv + b2[32 + lane];
    // LayerNorm over 64 channels (2 per lane)
    float sum = r0 + r1;
    #pragma unroll
    for (int d = 16; d; d >>= 1) sum += __shfl_xor_sync(0xFFFFFFFFu, sum, d);
    float mean = sum * (1.f / 64.f);
    float d0 = r0 - mean, d1 = r1 - mean;
    float sq = d0 * d0 + d1 * d1;
    #pragma unroll
    for (int d = 16; d; d >>= 1) sq += __shfl_xor_sync(0xFFFFFFFFu, sq, d);
    float rstd = rsqrtf(sq * (1.f / 64.f) + 1e-5f);
    out[dst * 64 + lane]      = d0 * rstd * gamma[lane]      + beta[lane];
    out[dst * 64 + 32 + lane] = d1 * rstd * gamma[32 + lane] + beta[32 + lane];
}

// ---------------- launch ----------------------------------------------------
extern "C" void kernel_launch(void* const* d_in, const int* in_sizes, int n_in,
                              void* d_out, int out_size) {
    const float *x = nullptr, *temb = nullptr, *W1 = nullptr, *W2 = nullptr;
    const int *ei = nullptr, *tids = nullptr;
    const float* v64[8] = {nullptr};
    int n64 = 0;
    for (int i = 0; i < n_in; i++) {
        switch (in_sizes[i]) {
            case 500000:  x    = (const float*)d_in[i]; break;
            case 6400000: ei   = (const int*)d_in[i];   break;
            case 100000:  tids = (const int*)d_in[i];   break;
            case 128:     temb = (const float*)d_in[i]; break;
            case 1344:    W1   = (const float*)d_in[i]; break;
            case 4096:    W2   = (const float*)d_in[i]; break;
            case 64:      if (n64 < 8) v64[n64++] = (const float*)d_in[i]; break;
            default: break;
        }
    }
    // relative order of 64-elem vectors is identical in dict order and signature order
    const float* as1 = v64[0]; const float* ad1 = v64[1]; const float* b1 = v64[2];
    const float* as2 = v64[3]; const float* ad2 = v64[4]; const float* b2 = v64[5];
    const float* gamma = v64[6]; const float* beta = v64[7];
    float* out = (float*)d_out;

    k_init   <<<(N_NODES + 255) / 256, 256>>>();
    k_hist   <<<(N_EDGES + 255) / 256, 256>>>(ei);
    k_scan   <<<1, 1024>>>();
    k_scatter<<<(E_TOT + 255) / 256, 256>>>(ei);
    k_node1  <<<(N_NODES + 3) / 4, 256>>>(x, tids, temb, W1, as1, ad1);
    k_agg1   <<<(N_NODES + 7) / 8, 256>>>(b1);
    k_node2  <<<(N_NODES + 3) / 4, 256>>>(W2, as2, ad2);
    k_agg2   <<<(N_NODES + 7) / 8, 256>>>(b2, gamma, beta, out);
}

// round 7
// speedup vs baseline: 1.2803x; 1.2803x over previous
#include <cuda_runtime.h>
#include <cuda_bf16.h>

#define N_NODES 100000
#define N_EDGES 3200000
#define E_TOT   (N_EDGES + N_NODES)
#define NEG_SLOPE 0.2f
#define N_TILES 98   // ceil(100000 / 1024)

// ---------------- device scratch (allocation-free contract) ----------------
__device__ int g_cnt[N_NODES];
__device__ int g_off[N_NODES + 1];
__device__ int g_cursor[N_NODES];
__device__ int g_csr_src[E_TOT];
__device__ int g_blk[N_TILES];
__device__ int g_blkoff[N_TILES];

__device__ __align__(16) float g_h1[N_NODES * 64];   // layer-1 node features
__device__ __align__(16) float g_al1[N_NODES * 4];   // [als0, als1, ald0, ald1]
__device__ __align__(16) float g_hin2[N_NODES * 64]; // relu(layer-1 out)
__device__ __align__(16) float g_h2[N_NODES * 64];   // layer-2 node features
__device__ __align__(8)  float g_al2[N_NODES * 2];   // [als, ald]

// ---------------- CSR build ----------------
__global__ void k_init() {
    int i = blockIdx.x * blockDim.x + threadIdx.x;
    if (i < N_NODES) g_cnt[i] = 1;   // self-loop pre-counted
}

__global__ void k_hist(const int* __restrict__ ei) {
    int e = blockIdx.x * blockDim.x + threadIdx.x;
    if (e < N_EDGES) atomicAdd(&g_cnt[ei[N_EDGES + e]], 1);   // dst row
}

// phase A: per-tile (1024) sums
__global__ void k_scan_a() {
    __shared__ int ws[32];
    int tid = threadIdx.x, lane = tid & 31, wid = tid >> 5;
    int i = blockIdx.x * 1024 + tid;
    int v = (i < N_NODES) ? g_cnt[i] : 0;
    #pragma unroll
    for (int d = 16; d; d >>= 1) v += __shfl_xor_sync(0xFFFFFFFFu, v, d);
    if (lane == 0) ws[wid] = v;
    __syncthreads();
    if (wid == 0) {
        int y = ws[lane];
        #pragma unroll
        for (int d = 16; d; d >>= 1) y += __shfl_xor_sync(0xFFFFFFFFu, y, d);
        if (lane == 0) g_blk[blockIdx.x] = y;
    }
}

// phase B: 1-warp exclusive scan of the 98 tile sums
__global__ void k_scan_b() {
    int lane = threadIdx.x;
    int carry = 0;
    for (int base = 0; base < N_TILES; base += 32) {
        int i = base + lane;
        int v = (i < N_TILES) ? g_blk[i] : 0;
        int x = v;
        #pragma unroll
        for (int d = 1; d < 32; d <<= 1) {
            int y = __shfl_up_sync(0xFFFFFFFFu, x, d);
            if (lane >= d) x += y;
        }
        if (i < N_TILES) g_blkoff[i] = x - v + carry;
        carry += __shfl_sync(0xFFFFFFFFu, x, 31);
    }
}

// phase C: per-tile exclusive rescan + tile offset
__global__ void k_scan_c() {
    __shared__ int warp_sums[32];
    int tid = threadIdx.x, lane = tid & 31, wid = tid >> 5;
    int i = blockIdx.x * 1024 + tid;
    int v = (i < N_NODES) ? g_cnt[i] : 0;
    int x = v;
    #pragma unroll
    for (int d = 1; d < 32; d <<= 1) {
        int y = __shfl_up_sync(0xFFFFFFFFu, x, d);
        if (lane >= d) x += y;
    }
    if (lane == 31) warp_sums[wid] = x;
    __syncthreads();
    if (wid == 0) {
        int y = warp_sums[lane];
        #pragma unroll
        for (int d = 1; d < 32; d <<= 1) {
            int z = __shfl_up_sync(0xFFFFFFFFu, y, d);
            if (lane >= d) y += z;
        }
        warp_sums[lane] = y;
    }
    __syncthreads();
    int excl = x - v + (wid ? warp_sums[wid - 1] : 0) + g_blkoff[blockIdx.x];
    if (i < N_NODES) { g_off[i] = excl; g_cursor[i] = excl; }
    if (i == 0) g_off[N_NODES] = E_TOT;
}

__global__ void k_scatter(const int* __restrict__ ei) {
    int e = blockIdx.x * blockDim.x + threadIdx.x;
    if (e >= E_TOT) return;
    int src, dst;
    if (e < N_EDGES) { src = ei[e]; dst = ei[N_EDGES + e]; }
    else             { src = dst = e - N_EDGES; }   // self loop
    int pos = atomicAdd(&g_cursor[dst], 1);
    g_csr_src[pos] = src;
}

// ---------------- layer 1: node transform (xin @ W1, attention scalars) ----
__global__ void k_node1(const float* __restrict__ x, const int* __restrict__ tids,
                        const float* __restrict__ temb, const float* __restrict__ W1,
                        const float* __restrict__ as1, const float* __restrict__ ad1) {
    __shared__ float sW[21 * 64];
    __shared__ float sxin[4][21];
    int t = threadIdx.x;
    for (int i = t; i < 21 * 64; i += 256) sW[i] = W1[i];
    int nl = t >> 6, c = t & 63;
    int node = blockIdx.x * 4 + nl;
    if (node < N_NODES && c < 21)
        sxin[nl][c] = (c < 5) ? x[node * 5 + c] : temb[tids[node] * 16 + (c - 5)];
    __syncthreads();
    if (node >= N_NODES) return;
    float h = 0.f;
    #pragma unroll
    for (int k = 0; k < 21; k++) h += sxin[nl][k] * sW[k * 64 + c];
    g_h1[node * 64 + c] = h;
    int head = c >> 5;
    float ps = h * as1[c], pd = h * ad1[c];
    #pragma unroll
    for (int d = 16; d; d >>= 1) {
        ps += __shfl_xor_sync(0xFFFFFFFFu, ps, d);
        pd += __shfl_xor_sync(0xFFFFFFFFu, pd, d);
    }
    if ((c & 31) == 0) {
        g_al1[node * 4 + head]     = ps;
        g_al1[node * 4 + 2 + head] = pd;
    }
}

// ---------------- layer 1 aggregation: warp/dst, shuffle-batched -----------
// Lane l owns channels [2l, 2l+1]; lanes 0-15 = head0, 16-31 = head1.
__global__ void k_agg1(const float* __restrict__ b1) {
    int w = (blockIdx.x * blockDim.x + threadIdx.x) >> 5;
    int lane = threadIdx.x & 31;
    if (w >= N_NODES) return;
    int dst = w;
    float ald0 = g_al1[dst * 4 + 2], ald1 = g_al1[dst * 4 + 3];
    int beg = g_off[dst], end = g_off[dst + 1];
    float2 acc = make_float2(0.f, 0.f);
    float sw0 = 0.f, sw1 = 0.f;
    for (int base = beg; base < end; base += 32) {
        int K = end - base; K = (K > 32) ? 32 : K;
        int myidx = 0; float w0 = 0.f, w1 = 0.f;
        if (lane < K) {
            myidx = __ldg(&g_csr_src[base + lane]);
            float4 a = *reinterpret_cast<const float4*>(&g_al1[myidx * 4]);
            float e0 = a.x + ald0; e0 = (e0 > 0.f) ? e0 : NEG_SLOPE * e0;
            float e1 = a.y + ald1; e1 = (e1 > 0.f) ? e1 : NEG_SLOPE * e1;
            w0 = __expf(e0); w1 = __expf(e1);
            sw0 += w0; sw1 += w1;
        }
        int j = 0;
        for (; j + 4 <= K; j += 4) {
            int s0 = __shfl_sync(0xFFFFFFFFu, myidx, j);
            int s1 = __shfl_sync(0xFFFFFFFFu, myidx, j + 1);
            int s2 = __shfl_sync(0xFFFFFFFFu, myidx, j + 2);
            int s3 = __shfl_sync(0xFFFFFFFFu, myidx, j + 3);
            float2 f0 = __ldg(reinterpret_cast<const float2*>(&g_h1[s0 * 64 + 2 * lane]));
            float2 f1 = __ldg(reinterpret_cast<const float2*>(&g_h1[s1 * 64 + 2 * lane]));
            float2 f2 = __ldg(reinterpret_cast<const float2*>(&g_h1[s2 * 64 + 2 * lane]));
            float2 f3 = __ldg(reinterpret_cast<const float2*>(&g_h1[s3 * 64 + 2 * lane]));
            float wa, wb, ws;
            wa = __shfl_sync(0xFFFFFFFFu, w0, j);     wb = __shfl_sync(0xFFFFFFFFu, w1, j);
            ws = (lane < 16) ? wa : wb; acc.x += ws * f0.x; acc.y += ws * f0.y;
            wa = __shfl_sync(0xFFFFFFFFu, w0, j + 1); wb = __shfl_sync(0xFFFFFFFFu, w1, j + 1);
            ws = (lane < 16) ? wa : wb; acc.x += ws * f1.x; acc.y += ws * f1.y;
            wa = __shfl_sync(0xFFFFFFFFu, w0, j + 2); wb = __shfl_sync(0xFFFFFFFFu, w1, j + 2);
            ws = (lane < 16) ? wa : wb; acc.x += ws * f2.x; acc.y += ws * f2.y;
            wa = __shfl_sync(0xFFFFFFFFu, w0, j + 3); wb = __shfl_sync(0xFFFFFFFFu, w1, j + 3);
            ws = (lane < 16) ? wa : wb; acc.x += ws * f3.x; acc.y += ws * f3.y;
        }
        for (; j < K; ++j) {
            int s = __shfl_sync(0xFFFFFFFFu, myidx, j);
            float wa = __shfl_sync(0xFFFFFFFFu, w0, j);
            float wb = __shfl_sync(0xFFFFFFFFu, w1, j);
            float ws = (lane < 16) ? wa : wb;
            float2 f = __ldg(reinterpret_cast<const float2*>(&g_h1[s * 64 + 2 * lane]));
            acc.x += ws * f.x; acc.y += ws * f.y;
        }
    }
    #pragma unroll
    for (int d = 16; d; d >>= 1) {
        sw0 += __shfl_xor_sync(0xFFFFFFFFu, sw0, d);
        sw1 += __shfl_xor_sync(0xFFFFFFFFu, sw1, d);
    }
    float inv = 1.f / (((lane < 16) ? sw0 : sw1) + 1e-16f);
    float r0 = acc.x * inv + b1[2 * lane];
    float r1 = acc.y * inv + b1[2 * lane + 1];
    float2 o = make_float2(fmaxf(r0, 0.f), fmaxf(r1, 0.f));
    *reinterpret_cast<float2*>(&g_hin2[dst * 64 + 2 * lane]) = o;
}

// ---------------- layer 2: node transform (hin2 @ W2, attention scalars) ---
__global__ void k_node2(const float* __restrict__ W2,
                        const float* __restrict__ as2, const float* __restrict__ ad2) {
    __shared__ float sW[64 * 64];
    __shared__ float shin[4][64];
    __shared__ float s_part[4][2][2];
    int t = threadIdx.x;
    for (int i = t; i < 64 * 64; i += 256) sW[i] = W2[i];
    int nl = t >> 6, c = t & 63;
    int node = blockIdx.x * 4 + nl;
    shin[nl][c] = g_hin2[node * 64 + c];
    __syncthreads();
    float h = 0.f;
    #pragma unroll
    for (int k = 0; k < 64; k++) h += shin[nl][k] * sW[k * 64 + c];
    g_h2[node * 64 + c] = h;
    float ps = h * as2[c], pd = h * ad2[c];
    #pragma unroll
    for (int d = 16; d; d >>= 1) {
        ps += __shfl_xor_sync(0xFFFFFFFFu, ps, d);
        pd += __shfl_xor_sync(0xFFFFFFFFu, pd, d);
    }
    if ((c & 31) == 0) { s_part[nl][c >> 5][0] = ps; s_part[nl][c >> 5][1] = pd; }
    __syncthreads();
    if (c == 0) {
        g_al2[node * 2 + 0] = s_part[nl][0][0] + s_part[nl][1][0];
        g_al2[node * 2 + 1] = s_part[nl][0][1] + s_part[nl][1][1];
    }
}

// ---------------- layer 2 aggregation + bias + LayerNorm -------------------
__global__ void k_agg2(const float* __restrict__ b2, const float* __restrict__ gamma,
                       const float* __restrict__ beta, float* __restrict__ out) {
    int w = (blockIdx.x * blockDim.x + threadIdx.x) >> 5;
    int lane = threadIdx.x & 31;
    if (w >= N_NODES) return;
    int dst = w;
    float ald = g_al2[dst * 2 + 1];
    int beg = g_off[dst], end = g_off[dst + 1];
    float2 acc = make_float2(0.f, 0.f);
    float sw = 0.f;
    for (int base = beg; base < end; base += 32) {
        int K = end - base; K = (K > 32) ? 32 : K;
        int myidx = 0; float w0 = 0.f;
        if (lane < K) {
            myidx = __ldg(&g_csr_src[base + lane]);
            float a = __ldg(&g_al2[myidx * 2]);
            float e = a + ald; e = (e > 0.f) ? e : NEG_SLOPE * e;
            w0 = __expf(e);
            sw += w0;
        }
        int j = 0;
        for (; j + 4 <= K; j += 4) {
            int s0 = __shfl_sync(0xFFFFFFFFu, myidx, j);
            int s1 = __shfl_sync(0xFFFFFFFFu, myidx, j + 1);
            int s2 = __shfl_sync(0xFFFFFFFFu, myidx, j + 2);
            int s3 = __shfl_sync(0xFFFFFFFFu, myidx, j + 3);
            float2 f0 = __ldg(reinterpret_cast<const float2*>(&g_h2[s0 * 64 + 2 * lane]));
            float2 f1 = __ldg(reinterpret_cast<const float2*>(&g_h2[s1 * 64 + 2 * lane]));
            float2 f2 = __ldg(reinterpret_cast<const float2*>(&g_h2[s2 * 64 + 2 * lane]));
            float2 f3 = __ldg(reinterpret_cast<const float2*>(&g_h2[s3 * 64 + 2 * lane]));
            float ws;
            ws = __shfl_sync(0xFFFFFFFFu, w0, j);     acc.x += ws * f0.x; acc.y += ws * f0.y;
            ws = __shfl_sync(0xFFFFFFFFu, w0, j + 1); acc.x += ws * f1.x; acc.y += ws * f1.y;
            ws = __shfl_sync(0xFFFFFFFFu, w0, j + 2); acc.x += ws * f2.x; acc.y += ws * f2.y;
            ws = __shfl_sync(0xFFFFFFFFu, w0, j + 3); acc.x += ws * f3.x; acc.y += ws * f3.y;
        }
        for (; j < K; ++j) {
            int s = __shfl_sync(0xFFFFFFFFu, myidx, j);
            float ws = __shfl_sync(0xFFFFFFFFu, w0, j);
            float2 f = __ldg(reinterpret_cast<const float2*>(&g_h2[s * 64 + 2 * lane]));
            acc.x += ws * f.x; acc.y += ws * f.y;
        }
    }
    #pragma unroll
    for (int d = 16; d; d >>= 1) sw += __shfl_xor_sync(0xFFFFFFFFu, sw, d);
    float inv = 1.f / (sw + 1e-16f);
    float r0 = acc.x * inv + b2[2 * lane];
    float r1 = acc.y * inv + b2[2 * lane + 1];
    // LayerNorm over 64 channels (2 per lane)
    float sum = r0 + r1;
    #pragma unroll
    for (int d = 16; d; d >>= 1) sum += __shfl_xor_sync(0xFFFFFFFFu, sum, d);
    float mean = sum * (1.f / 64.f);
    float d0 = r0 - mean, d1 = r1 - mean;
    float sq = d0 * d0 + d1 * d1;
    #pragma unroll
    for (int d = 16; d; d >>= 1) sq += __shfl_xor_sync(0xFFFFFFFFu, sq, d);
    float rstd = rsqrtf(sq * (1.f / 64.f) + 1e-5f);
    float2 o;
    o.x = d0 * rstd * gamma[2 * lane]     + beta[2 * lane];
    o.y = d1 * rstd * gamma[2 * lane + 1] + beta[2 * lane + 1];
    *reinterpret_cast<float2*>(&out[dst * 64 + 2 * lane]) = o;
}

// ---------------- launch ----------------------------------------------------
extern "C" void kernel_launch(void* const* d_in, const int* in_sizes, int n_in,
                              void* d_out, int out_size) {
    const float *x = nullptr, *temb = nullptr, *W1 = nullptr, *W2 = nullptr;
    const int *ei = nullptr, *tids = nullptr;
    const float* v64[8] = {nullptr};
    int n64 = 0;
    for (int i = 0; i < n_in; i++) {
        switch (in_sizes[i]) {
            case 500000:  x    = (const float*)d_in[i]; break;
            case 6400000: ei   = (const int*)d_in[i];   break;
            case 100000:  tids = (const int*)d_in[i];   break;
            case 128:     temb = (const float*)d_in[i]; break;
            case 1344:    W1   = (const float*)d_in[i]; break;
            case 4096:    W2   = (const float*)d_in[i]; break;
            case 64:      if (n64 < 8) v64[n64++] = (const float*)d_in[i]; break;
            default: break;
        }
    }
    const float* as1 = v64[0]; const float* ad1 = v64[1]; const float* b1 = v64[2];
    const float* as2 = v64[3]; const float* ad2 = v64[4]; const float* b2 = v64[5];
    const float* gamma = v64[6]; const float* beta = v64[7];
    float* out = (float*)d_out;

    k_init   <<<(N_NODES + 255) / 256, 256>>>();
    k_hist   <<<(N_EDGES + 255) / 256, 256>>>(ei);
    k_scan_a <<<N_TILES, 1024>>>();
    k_scan_b <<<1, 32>>>();
    k_scan_c <<<N_TILES, 1024>>>();
    k_scatter<<<(E_TOT + 255) / 256, 256>>>(ei);
    k_node1  <<<(N_NODES + 3) / 4, 256>>>(x, tids, temb, W1, as1, ad1);
    k_agg1   <<<(N_NODES + 7) / 8, 256>>>(b1);
    k_node2  <<<(N_NODES + 3) / 4, 256>>>(W2, as2, ad2);
    k_agg2   <<<(N_NODES + 7) / 8, 256>>>(b2, gamma, beta, out);
}

// round 8
// speedup vs baseline: 1.4403x; 1.1250x over previous
#include <cuda_runtime.h>
#include <cuda_fp16.h>
#include <cuda_bf16.h>

#define N_NODES 100000
#define N_EDGES 3200000
#define E_TOT   (N_EDGES + N_NODES)
#define NEG_SLOPE 0.2f
#define N_TILES 98   // ceil(100000 / 1024)

// ---------------- device scratch (allocation-free contract) ----------------
__device__ int g_cnt[N_NODES];
__device__ int g_off[N_NODES + 1];
__device__ int g_cursor[N_NODES];
__device__ int g_csr_src[E_TOT];
__device__ int g_blk[N_TILES];
__device__ int g_blkoff[N_TILES];

__device__ __align__(16) __half g_h1[N_NODES * 64];  // layer-1 features (half, gather table)
__device__ __align__(16) float g_al1[N_NODES * 4];   // [als0, als1, ald0, ald1]
__device__ __align__(16) float g_hin2[N_NODES * 64]; // relu(layer-1 out), fp32 for matmul
__device__ __align__(16) __half g_h2[N_NODES * 64];  // layer-2 features (half, gather table)
__device__ __align__(8)  float g_al2[N_NODES * 2];   // [als, ald]

// ---------------- CSR build ----------------
__global__ void k_init() {
    int i = blockIdx.x * blockDim.x + threadIdx.x;
    if (i < N_NODES) g_cnt[i] = 1;   // self-loop pre-counted
}

__global__ void k_hist(const int* __restrict__ ei) {
    int e = blockIdx.x * blockDim.x + threadIdx.x;
    if (e < N_EDGES) atomicAdd(&g_cnt[ei[N_EDGES + e]], 1);   // dst row
}

// phase A: per-tile (1024) sums
__global__ void k_scan_a() {
    __shared__ int ws[32];
    int tid = threadIdx.x, lane = tid & 31, wid = tid >> 5;
    int i = blockIdx.x * 1024 + tid;
    int v = (i < N_NODES) ? g_cnt[i] : 0;
    #pragma unroll
    for (int d = 16; d; d >>= 1) v += __shfl_xor_sync(0xFFFFFFFFu, v, d);
    if (lane == 0) ws[wid] = v;
    __syncthreads();
    if (wid == 0) {
        int y = ws[lane];
        #pragma unroll
        for (int d = 16; d; d >>= 1) y += __shfl_xor_sync(0xFFFFFFFFu, y, d);
        if (lane == 0) g_blk[blockIdx.x] = y;
    }
}

// phase B: 1-warp exclusive scan of the 98 tile sums
__global__ void k_scan_b() {
    int lane = threadIdx.x;
    int carry = 0;
    for (int base = 0; base < N_TILES; base += 32) {
        int i = base + lane;
        int v = (i < N_TILES) ? g_blk[i] : 0;
        int x = v;
        #pragma unroll
        for (int d = 1; d < 32; d <<= 1) {
            int y = __shfl_up_sync(0xFFFFFFFFu, x, d);
            if (lane >= d) x += y;
        }
        if (i < N_TILES) g_blkoff[i] = x - v + carry;
        carry += __shfl_sync(0xFFFFFFFFu, x, 31);
    }
}

// phase C: per-tile exclusive rescan + tile offset
__global__ void k_scan_c() {
    __shared__ int warp_sums[32];
    int tid = threadIdx.x, lane = tid & 31, wid = tid >> 5;
    int i = blockIdx.x * 1024 + tid;
    int v = (i < N_NODES) ? g_cnt[i] : 0;
    int x = v;
    #pragma unroll
    for (int d = 1; d < 32; d <<= 1) {
        int y = __shfl_up_sync(0xFFFFFFFFu, x, d);
        if (lane >= d) x += y;
    }
    if (lane == 31) warp_sums[wid] = x;
    __syncthreads();
    if (wid == 0) {
        int y = warp_sums[lane];
        #pragma unroll
        for (int d = 1; d < 32; d <<= 1) {
            int z = __shfl_up_sync(0xFFFFFFFFu, y, d);
            if (lane >= d) y += z;
        }
        warp_sums[lane] = y;
    }
    __syncthreads();
    int excl = x - v + (wid ? warp_sums[wid - 1] : 0) + g_blkoff[blockIdx.x];
    if (i < N_NODES) { g_off[i] = excl; g_cursor[i] = excl; }
    if (i == 0) g_off[N_NODES] = E_TOT;
}

__global__ void k_scatter(const int* __restrict__ ei) {
    int e = blockIdx.x * blockDim.x + threadIdx.x;
    if (e >= E_TOT) return;
    int src, dst;
    if (e < N_EDGES) { src = ei[e]; dst = ei[N_EDGES + e]; }
    else             { src = dst = e - N_EDGES; }   // self loop
    int pos = atomicAdd(&g_cursor[dst], 1);
    g_csr_src[pos] = src;
}

// ---------------- layer 1: node transform (xin @ W1, attention scalars) ----
__global__ void k_node1(const float* __restrict__ x, const int* __restrict__ tids,
                        const float* __restrict__ temb, const float* __restrict__ W1,
                        const float* __restrict__ as1, const float* __restrict__ ad1) {
    __shared__ float sW[21 * 64];
    __shared__ float sxin[4][21];
    int t = threadIdx.x;
    for (int i = t; i < 21 * 64; i += 256) sW[i] = W1[i];
    int nl = t >> 6, c = t & 63;
    int node = blockIdx.x * 4 + nl;
    if (node < N_NODES && c < 21)
        sxin[nl][c] = (c < 5) ? x[node * 5 + c] : temb[tids[node] * 16 + (c - 5)];
    __syncthreads();
    if (node >= N_NODES) return;
    float h = 0.f;
    #pragma unroll
    for (int k = 0; k < 21; k++) h += sxin[nl][k] * sW[k * 64 + c];
    g_h1[node * 64 + c] = __float2half_rn(h);
    int head = c >> 5;
    float ps = h * as1[c], pd = h * ad1[c];
    #pragma unroll
    for (int d = 16; d; d >>= 1) {
        ps += __shfl_xor_sync(0xFFFFFFFFu, ps, d);
        pd += __shfl_xor_sync(0xFFFFFFFFu, pd, d);
    }
    if ((c & 31) == 0) {
        g_al1[node * 4 + head]     = ps;
        g_al1[node * 4 + 2 + head] = pd;
    }
}

// ---------------- layer 1 aggregation: warp/dst, shuffle-batched -----------
// Lane l owns channels [2l, 2l+1]; lanes 0-15 = head0, 16-31 = head1.
__global__ void k_agg1(const float* __restrict__ b1) {
    int w = (blockIdx.x * blockDim.x + threadIdx.x) >> 5;
    int lane = threadIdx.x & 31;
    if (w >= N_NODES) return;
    int dst = w;
    float ald0 = g_al1[dst * 4 + 2], ald1 = g_al1[dst * 4 + 3];
    int beg = g_off[dst], end = g_off[dst + 1];
    float2 acc = make_float2(0.f, 0.f);
    float sw0 = 0.f, sw1 = 0.f;
    for (int base = beg; base < end; base += 32) {
        int K = end - base; K = (K > 32) ? 32 : K;
        int myidx = 0; float w0 = 0.f, w1 = 0.f;
        if (lane < K) {
            myidx = __ldg(&g_csr_src[base + lane]);
            float4 a = *reinterpret_cast<const float4*>(&g_al1[myidx * 4]);
            float e0 = a.x + ald0; e0 = (e0 > 0.f) ? e0 : NEG_SLOPE * e0;
            float e1 = a.y + ald1; e1 = (e1 > 0.f) ? e1 : NEG_SLOPE * e1;
            w0 = __expf(e0); w1 = __expf(e1);
            sw0 += w0; sw1 += w1;
        }
        int j = 0;
        for (; j + 4 <= K; j += 4) {
            int s0 = __shfl_sync(0xFFFFFFFFu, myidx, j);
            int s1 = __shfl_sync(0xFFFFFFFFu, myidx, j + 1);
            int s2 = __shfl_sync(0xFFFFFFFFu, myidx, j + 2);
            int s3 = __shfl_sync(0xFFFFFFFFu, myidx, j + 3);
            __half2 h0 = __ldg(reinterpret_cast<const __half2*>(&g_h1[s0 * 64 + 2 * lane]));
            __half2 h1 = __ldg(reinterpret_cast<const __half2*>(&g_h1[s1 * 64 + 2 * lane]));
            __half2 h2 = __ldg(reinterpret_cast<const __half2*>(&g_h1[s2 * 64 + 2 * lane]));
            __half2 h3 = __ldg(reinterpret_cast<const __half2*>(&g_h1[s3 * 64 + 2 * lane]));
            float2 f0 = __half22float2(h0);
            float2 f1 = __half22float2(h1);
            float2 f2 = __half22float2(h2);
            float2 f3 = __half22float2(h3);
            float wa, wb, ws;
            wa = __shfl_sync(0xFFFFFFFFu, w0, j);     wb = __shfl_sync(0xFFFFFFFFu, w1, j);
            ws = (lane < 16) ? wa : wb; acc.x += ws * f0.x; acc.y += ws * f0.y;
            wa = __shfl_sync(0xFFFFFFFFu, w0, j + 1); wb = __shfl_sync(0xFFFFFFFFu, w1, j + 1);
            ws = (lane < 16) ? wa : wb; acc.x += ws * f1.x; acc.y += ws * f1.y;
            wa = __shfl_sync(0xFFFFFFFFu, w0, j + 2); wb = __shfl_sync(0xFFFFFFFFu, w1, j + 2);
            ws = (lane < 16) ? wa : wb; acc.x += ws * f2.x; acc.y += ws * f2.y;
            wa = __shfl_sync(0xFFFFFFFFu, w0, j + 3); wb = __shfl_sync(0xFFFFFFFFu, w1, j + 3);
            ws = (lane < 16) ? wa : wb; acc.x += ws * f3.x; acc.y += ws * f3.y;
        }
        for (; j < K; ++j) {
            int s = __shfl_sync(0xFFFFFFFFu, myidx, j);
            float wa = __shfl_sync(0xFFFFFFFFu, w0, j);
            float wb = __shfl_sync(0xFFFFFFFFu, w1, j);
            float ws = (lane < 16) ? wa : wb;
            float2 f = __half22float2(
                __ldg(reinterpret_cast<const __half2*>(&g_h1[s * 64 + 2 * lane])));
            acc.x += ws * f.x; acc.y += ws * f.y;
        }
    }
    #pragma unroll
    for (int d = 16; d; d >>= 1) {
        sw0 += __shfl_xor_sync(0xFFFFFFFFu, sw0, d);
        sw1 += __shfl_xor_sync(0xFFFFFFFFu, sw1, d);
    }
    float inv = 1.f / (((lane < 16) ? sw0 : sw1) + 1e-16f);
    float r0 = acc.x * inv + b1[2 * lane];
    float r1 = acc.y * inv + b1[2 * lane + 1];
    float2 o = make_float2(fmaxf(r0, 0.f), fmaxf(r1, 0.f));
    *reinterpret_cast<float2*>(&g_hin2[dst * 64 + 2 * lane]) = o;
}

// ---------------- layer 2: node transform (hin2 @ W2, attention scalars) ---
__global__ void k_node2(const float* __restrict__ W2,
                        const float* __restrict__ as2, const float* __restrict__ ad2) {
    __shared__ float sW[64 * 64];
    __shared__ float shin[4][64];
    __shared__ float s_part[4][2][2];
    int t = threadIdx.x;
    for (int i = t; i < 64 * 64; i += 256) sW[i] = W2[i];
    int nl = t >> 6, c = t & 63;
    int node = blockIdx.x * 4 + nl;
    shin[nl][c] = g_hin2[node * 64 + c];
    __syncthreads();
    float h = 0.f;
    #pragma unroll
    for (int k = 0; k < 64; k++) h += shin[nl][k] * sW[k * 64 + c];
    g_h2[node * 64 + c] = __float2half_rn(h);
    float ps = h * as2[c], pd = h * ad2[c];
    #pragma unroll
    for (int d = 16; d; d >>= 1) {
        ps += __shfl_xor_sync(0xFFFFFFFFu, ps, d);
        pd += __shfl_xor_sync(0xFFFFFFFFu, pd, d);
    }
    if ((c & 31) == 0) { s_part[nl][c >> 5][0] = ps; s_part[nl][c >> 5][1] = pd; }
    __syncthreads();
    if (c == 0) {
        g_al2[node * 2 + 0] = s_part[nl][0][0] + s_part[nl][1][0];
        g_al2[node * 2 + 1] = s_part[nl][0][1] + s_part[nl][1][1];
    }
}

// ---------------- layer 2 aggregation + bias + LayerNorm -------------------
__global__ void k_agg2(const float* __restrict__ b2, const float* __restrict__ gamma,
                       const float* __restrict__ beta, float* __restrict__ out) {
    int w = (blockIdx.x * blockDim.x + threadIdx.x) >> 5;
    int lane = threadIdx.x & 31;
    if (w >= N_NODES) return;
    int dst = w;
    float ald = g_al2[dst * 2 + 1];
    int beg = g_off[dst], end = g_off[dst + 1];
    float2 acc = make_float2(0.f, 0.f);
    float sw = 0.f;
    for (int base = beg; base < end; base += 32) {
        int K = end - base; K = (K > 32) ? 32 : K;
        int myidx = 0; float w0 = 0.f;
        if (lane < K) {
            myidx = __ldg(&g_csr_src[base + lane]);
            float a = __ldg(&g_al2[myidx * 2]);
            float e = a + ald; e = (e > 0.f) ? e : NEG_SLOPE * e;
            w0 = __expf(e);
            sw += w0;
        }
        int j = 0;
        for (; j + 4 <= K; j += 4) {
            int s0 = __shfl_sync(0xFFFFFFFFu, myidx, j);
            int s1 = __shfl_sync(0xFFFFFFFFu, myidx, j + 1);
            int s2 = __shfl_sync(0xFFFFFFFFu, myidx, j + 2);
            int s3 = __shfl_sync(0xFFFFFFFFu, myidx, j + 3);
            __half2 h0 = __ldg(reinterpret_cast<const __half2*>(&g_h2[s0 * 64 + 2 * lane]));
            __half2 h1 = __ldg(reinterpret_cast<const __half2*>(&g_h2[s1 * 64 + 2 * lane]));
            __half2 h2 = __ldg(reinterpret_cast<const __half2*>(&g_h2[s2 * 64 + 2 * lane]));
            __half2 h3 = __ldg(reinterpret_cast<const __half2*>(&g_h2[s3 * 64 + 2 * lane]));
            float2 f0 = __half22float2(h0);
            float2 f1 = __half22float2(h1);
            float2 f2 = __half22float2(h2);
            float2 f3 = __half22float2(h3);
            float ws;
            ws = __shfl_sync(0xFFFFFFFFu, w0, j);     acc.x += ws * f0.x; acc.y += ws * f0.y;
            ws = __shfl_sync(0xFFFFFFFFu, w0, j + 1); acc.x += ws * f1.x; acc.y += ws * f1.y;
            ws = __shfl_sync(0xFFFFFFFFu, w0, j + 2); acc.x += ws * f2.x; acc.y += ws * f2.y;
            ws = __shfl_sync(0xFFFFFFFFu, w0, j + 3); acc.x += ws * f3.x; acc.y += ws * f3.y;
        }
        for (; j < K; ++j) {
            int s = __shfl_sync(0xFFFFFFFFu, myidx, j);
            float ws = __shfl_sync(0xFFFFFFFFu, w0, j);
            float2 f = __half22float2(
                __ldg(reinterpret_cast<const __half2*>(&g_h2[s * 64 + 2 * lane])));
            acc.x += ws * f.x; acc.y += ws * f.y;
        }
    }
    #pragma unroll
    for (int d = 16; d; d >>= 1) sw += __shfl_xor_sync(0xFFFFFFFFu, sw, d);
    float inv = 1.f / (sw + 1e-16f);
    float r0 = acc.x * inv + b2[2 * lane];
    float r1 = acc.y * inv + b2[2 * lane + 1];
    // LayerNorm over 64 channels (2 per lane)
    float sum = r0 + r1;
    #pragma unroll
    for (int d = 16; d; d >>= 1) sum += __shfl_xor_sync(0xFFFFFFFFu, sum, d);
    float mean = sum * (1.f / 64.f);
    float d0 = r0 - mean, d1 = r1 - mean;
    float sq = d0 * d0 + d1 * d1;
    #pragma unroll
    for (int d = 16; d; d >>= 1) sq += __shfl_xor_sync(0xFFFFFFFFu, sq, d);
    float rstd = rsqrtf(sq * (1.f / 64.f) + 1e-5f);
    float2 o;
    o.x = d0 * rstd * gamma[2 * lane]     + beta[2 * lane];
    o.y = d1 * rstd * gamma[2 * lane + 1] + beta[2 * lane + 1];
    *reinterpret_cast<float2*>(&out[dst * 64 + 2 * lane]) = o;
}

// ---------------- launch ----------------------------------------------------
extern "C" void kernel_launch(void* const* d_in, const int* in_sizes, int n_in,
                              void* d_out, int out_size) {
    const float *x = nullptr, *temb = nullptr, *W1 = nullptr, *W2 = nullptr;
    const int *ei = nullptr, *tids = nullptr;
    const float* v64[8] = {nullptr};
    int n64 = 0;
    for (int i = 0; i < n_in; i++) {
        switch (in_sizes[i]) {
            case 500000:  x    = (const float*)d_in[i]; break;
            case 6400000: ei   = (const int*)d_in[i];   break;
            case 100000:  tids = (const int*)d_in[i];   break;
            case 128:     temb = (const float*)d_in[i]; break;
            case 1344:    W1   = (const float*)d_in[i]; break;
            case 4096:    W2   = (const float*)d_in[i]; break;
            case 64:      if (n64 < 8) v64[n64++] = (const float*)d_in[i]; break;
            default: break;
        }
    }
    const float* as1 = v64[0]; const float* ad1 = v64[1]; const float* b1 = v64[2];
    const float* as2 = v64[3]; const float* ad2 = v64[4]; const float* b2 = v64[5];
    const float* gamma = v64[6]; const float* beta = v64[7];
    float* out = (float*)d_out;

    k_init   <<<(N_NODES + 255) / 256, 256>>>();
    k_hist   <<<(N_EDGES + 255) / 256, 256>>>(ei);
    k_scan_a <<<N_TILES, 1024>>>();
    k_scan_b <<<1, 32>>>();
    k_scan_c <<<N_TILES, 1024>>>();
    k_scatter<<<(E_TOT + 255) / 256, 256>>>(ei);
    k_node1  <<<(N_NODES + 3) / 4, 256>>>(x, tids, temb, W1, as1, ad1);
    k_agg1   <<<(N_NODES + 7) / 8, 256>>>(b1);
    k_node2  <<<(N_NODES + 3) / 4, 256>>>(W2, as2, ad2);
    k_agg2   <<<(N_NODES + 7) / 8, 256>>>(b2, gamma, beta, out);
}